// round 14
// baseline (speedup 1.0000x reference)
#include <cuda_runtime.h>
#include <math.h>
#include <stdint.h>

#define DTF       1e-4f
#define TSTEPS    4000000
#define TPB       256
#define STEPS_PER_CTA 2048
#define NCTA      1954            /* ceil(4e6/2048) */
#define NWTILE    (NCTA*8)        /* 256-step warp tiles */

// pass3 smem geometry (float4 units) — one buffer, input then output
#define IN_ROW    7               /* 6 payload f4 + 1 pad */
#define WARP_IN   (32*IN_ROW)     /* 224 f4 = 3584 B */
#define P3_SMEM   (8*WARP_IN*16)  /* 28672 B */

struct SC {
    float t00,t01,t10,t11;     // Trans
    float xi00,xi01,xi10,xi11; // XiCov
    float c00,c01,c10,c11;     // Cout
    float p0dt, p1, x00, x01;
    float cA, sA;              // 1-step forcing rotation
    float cR, sR;              // 32-step forcing rotation
    float Tpow[22][4];         // Tpow[r] = Trans^(2^r)
};

__device__ float2   g_wagg[NWTILE];   // per-warp (256-step) affine aggregate
__device__ float    g_csum[NCTA*2];   // per-tile affine aggregate
__device__ float    g_centry[NCTA*2]; // per-tile entry state
__device__ unsigned g_done;           // zero-init at load; reset by last CTA

__device__ __forceinline__ void mat2mul(const float* a, const float* b, float* o) {
    o[0]=fmaf(a[0],b[0],a[1]*b[2]); o[1]=fmaf(a[0],b[1],a[1]*b[3]);
    o[2]=fmaf(a[2],b[0],a[3]*b[2]); o[3]=fmaf(a[2],b[1],a[3]*b[3]);
}

// Recompute all derived constants (deterministic, bit-identical per CTA).
__device__ __forceinline__ void compute_consts(
    SC* s, int maxPow,
    const float* __restrict__ A, const float* __restrict__ B,
    const float* __restrict__ E, const float* __restrict__ cov,
    const float* __restrict__ tp, const float* __restrict__ ini)
{
    float a0=A[0],a1=A[1],a2=A[2],a3=A[3];
    float b0=B[0],b1=B[1],b2=B[2],b3=B[3];
    float e0=E[0],e1=E[1],e2=E[2],e3=E[3];
    float v0=cov[0],v1=cov[1],v2=cov[2],v3=cov[3];
    float s2 = sqrtf(2.0f);
    float cb0=fmaf(v0,b0,v1*b2), cb1=fmaf(v0,b1,v1*b3);
    float cb2=fmaf(v2,b0,v3*b2), cb3=fmaf(v2,b1,v3*b3);
    float xi0=(e0-cb0)/s2, xi1=(e1-cb1)/s2, xi2=(e2-cb2)/s2, xi3=(e3-cb3)/s2;
    float n0=-s2*b0, n1=-s2*b2, n2=-s2*b1, n3=-s2*b3;
    float xc0=fmaf(xi0,n0,xi1*n2), xc1=fmaf(xi0,n1,xi1*n3);
    float xc2=fmaf(xi2,n0,xi3*n2), xc3=fmaf(xi2,n1,xi3*n3);
    float tr[4] = { 1.0f + (a0-xc0)*DTF, (a1-xc1)*DTF,
                    (a2-xc2)*DTF, 1.0f + (a3-xc3)*DTF };
    s->t00=tr[0]; s->t01=tr[1]; s->t10=tr[2]; s->t11=tr[3];
    s->xi00=xi0; s->xi01=xi1; s->xi10=xi2; s->xi11=xi3;
    s->c00=n0*DTF; s->c01=n1*DTF; s->c10=n2*DTF; s->c11=n3*DTF;
    float p1f = tp[1];
    s->p0dt = tp[0]*DTF;
    s->p1   = p1f;
    s->x00  = ini[0]; s->x01 = ini[1];
    { float sr,cr; sincosf(p1f*DTF, &sr,&cr);        s->cA=cr; s->sA=sr; }
    { float sr,cr; sincosf(p1f*(DTF*32.f), &sr,&cr); s->cR=cr; s->sR=sr; }
    for (int i=0;i<4;i++) s->Tpow[0][i]=tr[i];
    for (int r=1;r<=maxPow;r++) mat2mul(s->Tpow[r-1], s->Tpow[r-1], s->Tpow[r]);
}

// One simulated step: update state (x0,x1) with forcing rotation (cc,ss).
#define UPSTATE(d0,d1) do{                                            \
    float a0_ = fmaf(xi01,(d1),cc);  a0_ = fmaf(xi00,(d0),a0_);        \
    float a1_ = xi11*(d1);           a1_ = fmaf(xi10,(d0),a1_);        \
    float nx0_ = fmaf(t01,x1,a0_);   nx0_ = fmaf(t00,x0,nx0_);         \
    float nx1_ = fmaf(t11,x1,a1_);   nx1_ = fmaf(t10,x0,nx1_);         \
    x0=nx0_; x1=nx1_;                                                  \
    float nc_ = fmaf(cc,cA,-(ss*sA)); ss = fmaf(ss,cA,cc*sA); cc=nc_;  \
} while(0)

// ------------------------------------------------- pass1 (+fused pass2) ----
// NOTE: no min-blocks cap — the fused pass2 epilogue needs the registers
// (capping at 6 CTAs/SM caused spills and a ~2us regression in R12/R13).
__global__ void __launch_bounds__(TPB) k_pass1(const float* __restrict__ in,
    const float* __restrict__ A, const float* __restrict__ B,
    const float* __restrict__ E, const float* __restrict__ cov,
    const float* __restrict__ tp, const float* __restrict__ ini)
{
    __shared__ SC sC;
    __shared__ float2 swarp[8];
    __shared__ float  sc[TPB], sd[TPB];
    __shared__ int    s_last;
    const int tid = threadIdx.x, blk = blockIdx.x;
    const int lane = tid & 31, wid = tid >> 5;
    const int warpBase = blk*STEPS_PER_CTA + wid*256;

    if (tid==0) compute_consts(&sC, 21, A,B,E,cov,tp,ini);
    __syncthreads();

    const float xi00=sC.xi00,xi01=sC.xi01,xi10=sC.xi10,xi11=sC.xi11;
    const float M0=sC.Tpow[5][0],M1=sC.Tpow[5][1],M2=sC.Tpow[5][2],M3=sC.Tpow[5][3];
    const float cR=sC.cR, sR=sC.sR, p0dt=sC.p0dt;

    // forcing seed: inline fp32 phase (bit-matches reference t channel)
    float sv, cv;
    sincosf(sC.p1 * ((float)(warpBase+lane) * DTF), &sv, &cv);
    float cc = p0dt*cv, ss = p0dt*sv;

    float S0=0.f, S1=0.f;
    const float* p = in + (size_t)warpBase*3 + lane*3;
    #pragma unroll
    for (int j=0;j<8;j++){
        int k = warpBase + 32*j + lane;
        float b0=0.f, b1=0.f;
        if (k < TSTEPS){
            float d0 = p[96*j+1];
            float d1 = p[96*j+2];
            b0 = fmaf(xi00,d0, fmaf(xi01,d1, cc));
            b1 = fmaf(xi10,d0, xi11*d1);
        }
        float n0 = fmaf(M0,S0, fmaf(M1,S1, b0));
        float n1 = fmaf(M2,S0, fmaf(M3,S1, b1));
        S0=n0; S1=n1;
        float nc = fmaf(cc,cR,-(ss*sR)); ss = fmaf(ss,cR,cc*sR); cc=nc;
    }

    // in-warp weighted butterfly: R <- M^(2^r)*R + R[lane+2^r]
    #pragma unroll
    for (int r=0;r<5;r++){
        float u0=__shfl_down_sync(0xffffffffu,S0,1<<r);
        float u1=__shfl_down_sync(0xffffffffu,S1,1<<r);
        float P0=sC.Tpow[r][0],P1=sC.Tpow[r][1],P2=sC.Tpow[r][2],P3=sC.Tpow[r][3];
        float n0 = fmaf(P0,S0, fmaf(P1,S1, u0));
        float n1 = fmaf(P2,S0, fmaf(P3,S1, u1));
        S0=n0; S1=n1;
    }
    if (lane==0){
        g_wagg[blk*8+wid] = make_float2(S0,S1);
        swarp[wid] = make_float2(S0,S1);
    }
    __syncthreads();
    if (wid==0 && lane<8){
        float2 R = swarp[lane];
        float R0=R.x, R1=R.y;
        #pragma unroll
        for (int r=0;r<3;r++){
            float u0=__shfl_down_sync(0x000000ffu,R0,1<<r);
            float u1=__shfl_down_sync(0x000000ffu,R1,1<<r);
            float P0=sC.Tpow[8+r][0],P1=sC.Tpow[8+r][1],P2=sC.Tpow[8+r][2],P3=sC.Tpow[8+r][3];
            float n0 = fmaf(P0,R0, fmaf(P1,R1, u0));
            float n1 = fmaf(P2,R0, fmaf(P3,R1, u1));
            R0=n0; R1=n1;
        }
        if (lane==0){
            g_csum[2*blk]=R0; g_csum[2*blk+1]=R1;
            __threadfence();
            unsigned t = atomicAdd(&g_done, 1u);
            if (t == NCTA-1u){ s_last = 1; g_done = 0u; }   // reset for next replay
            else s_last = 0;
        }
    }
    __syncthreads();
    if (!s_last) return;

    // ================= fused pass2 (last CTA, 256 threads) =================
    __threadfence();
    const int g = tid;                     // chunk of 8 tiles: [8g, 8g+8)
    const float Tc0=sC.Tpow[11][0],Tc1=sC.Tpow[11][1],
                Tc2=sC.Tpow[11][2],Tc3=sC.Tpow[11][3];
    float a[8][2];
    float v0=0.f, v1=0.f;
    #pragma unroll
    for (int i=0;i<8;i++){
        int t8 = 8*g+i;
        float a0 = (t8<NCTA)? __ldcg(&g_csum[2*t8])   : 0.f;
        float a1 = (t8<NCTA)? __ldcg(&g_csum[2*t8+1]) : 0.f;
        a[i][0]=a0; a[i][1]=a1;
        float n0 = fmaf(Tc0,v0, fmaf(Tc1,v1, a0));
        float n1 = fmaf(Tc2,v0, fmaf(Tc3,v1, a1));
        v0=n0; v1=n1;
    }
    sc[g]=v0; sd[g]=v1;
    __syncthreads();
    #pragma unroll
    for (int r=0;r<8;r++){
        int off = 1<<r;
        float u0=0.f, u1=0.f;
        if (g>=off){ u0=sc[g-off]; u1=sd[g-off]; }
        __syncthreads();
        float P0=sC.Tpow[14+r][0],P1=sC.Tpow[14+r][1],P2=sC.Tpow[14+r][2],P3=sC.Tpow[14+r][3];
        v0 = fmaf(P0,u0,fmaf(P1,u1,v0));
        v1 = fmaf(P2,u0,fmaf(P3,u1,v1));
        sc[g]=v0; sd[g]=v1;
        __syncthreads();
    }
    float pe0 = g ? sc[g-1] : 0.f;
    float pe1 = g ? sd[g-1] : 0.f;
    float X0=sC.x00, X1=sC.x01;
    #pragma unroll
    for (int r=0;r<8;r++) if ((g>>r)&1){
        float P0=sC.Tpow[14+r][0],P1=sC.Tpow[14+r][1],P2=sC.Tpow[14+r][2],P3=sC.Tpow[14+r][3];
        float n0=fmaf(P0,X0,P1*X1), n1=fmaf(P2,X0,P3*X1);
        X0=n0; X1=n1;
    }
    float E0 = pe0 + X0, E1 = pe1 + X1;    // entry of tile 8g
    #pragma unroll
    for (int i=0;i<8;i++){
        int t8 = 8*g+i;
        if (t8<NCTA){ g_centry[2*t8]=E0; g_centry[2*t8+1]=E1; }
        float n0 = fmaf(Tc0,E0, fmaf(Tc1,E1, a[i][0]));
        float n1 = fmaf(Tc2,E0, fmaf(Tc3,E1, a[i][1]));
        E0=n0; E1=n1;
    }
}

// ---------------------------------------------------------------- pass3 ----
__global__ void __launch_bounds__(TPB,5) k_pass3(const float* __restrict__ in,
    float* __restrict__ out,
    const float* __restrict__ A, const float* __restrict__ B,
    const float* __restrict__ E, const float* __restrict__ cov,
    const float* __restrict__ tp, const float* __restrict__ ini)
{
    extern __shared__ float4 s4[];
    __shared__ SC sC;
    const int tid = threadIdx.x, blk = blockIdx.x;
    const int lane = tid & 31, wid = tid >> 5;

    const int warpStepBase = blk*STEPS_PER_CTA + wid*256;
    const bool wfull = (warpStepBase + 256 <= TSTEPS);

    float4* sin4 = s4 + wid*WARP_IN;   // input stage, then reused as output stage

    // ---- async stage input FIRST (needs no constants; hides const compute) ----
    if (wfull){
        uint32_t sbase;
        asm("{ .reg .u64 t; cvta.to.shared.u64 t, %1; cvt.u32.u64 %0, t; }"
            : "=r"(sbase) : "l"(sin4));
        const float4* p4 = (const float4*)in + (size_t)warpStepBase*3/4;
        #pragma unroll
        for (int i=0;i<6;i++){
            int q = lane + 32*i;
            int to = q/6, c = q - to*6;
            uint32_t dst = sbase + (uint32_t)(to*IN_ROW + c)*16u;
            asm volatile("cp.async.cg.shared.global [%0],[%1],16;"
                         :: "r"(dst), "l"(p4+q));
        }
        asm volatile("cp.async.commit_group;" ::: "memory");
    }

    if (tid==0) compute_consts(&sC, 10, A,B,E,cov,tp,ini);
    __syncthreads();
    if (!wfull) return;

    const float t00=sC.t00,t01=sC.t01,t10=sC.t10,t11=sC.t11;
    const float xi00=sC.xi00,xi01=sC.xi01,xi10=sC.xi10,xi11=sC.xi11;
    const float c00=sC.c00,c01=sC.c01,c10=sC.c10,c11=sC.c11;
    const float cA=sC.cA, sA=sC.sA, p0dt=sC.p0dt;

    // ---- warp entry: E_w = (M^256)^wid * tile_entry + prefix of warp aggs ----
    float We0, We1;
    {
        float w0=0.f, w1=0.f;
        if (lane < 8){ float2 wa = g_wagg[blk*8+lane]; w0=wa.x; w1=wa.y; }
        #pragma unroll
        for (int r=0;r<3;r++){
            int off = 1<<r;
            float u0=__shfl_up_sync(0xffffffffu,w0,off);
            float u1=__shfl_up_sync(0xffffffffu,w1,off);
            if (lane>=off){
                float P0=sC.Tpow[8+r][0],P1=sC.Tpow[8+r][1],P2=sC.Tpow[8+r][2],P3=sC.Tpow[8+r][3];
                w0 = fmaf(P0,u0,fmaf(P1,u1,w0));
                w1 = fmaf(P2,u0,fmaf(P3,u1,w1));
            }
        }
        float pf0=__shfl_up_sync(0xffffffffu,w0,1);
        float pf1=__shfl_up_sync(0xffffffffu,w1,1);
        if (lane==0){ pf0=0.f; pf1=0.f; }
        float X0=g_centry[2*blk], X1=g_centry[2*blk+1];
        #pragma unroll
        for (int r=0;r<3;r++) if ((lane>>r)&1){
            float P0=sC.Tpow[8+r][0],P1=sC.Tpow[8+r][1],P2=sC.Tpow[8+r][2],P3=sC.Tpow[8+r][3];
            float n0=fmaf(P0,X0,P1*X1), n1=fmaf(P2,X0,P3*X1);
            X0=n0; X1=n1;
        }
        float e0 = X0 + pf0, e1 = X1 + pf1;
        We0 = __shfl_sync(0xffffffffu, e0, wid);
        We1 = __shfl_sync(0xffffffffu, e1, wid);
    }

    asm volatile("cp.async.wait_group 0;" ::: "memory");
    __syncwarp();

    // ---- offset pass from x=0, recording intermediate offset states ----
    float ox[8], oy[8];
    float x0=0.f, x1=0.f;
    float cc, ss;
    {
        const float4* row = sin4 + lane*IN_ROW;
        float4 a0v=row[0], b0v=row[1], c0v=row[2];
        float4 a1v=row[3], b1v=row[4], c1v=row[5];
        float sv, cvv; sincosf(sC.p1 * a0v.x, &sv, &cvv);
        cc = p0dt*cvv; ss = p0dt*sv;
        ox[0]=0.f;  oy[0]=0.f;   UPSTATE(a0v.y,a0v.z);
        ox[1]=x0;   oy[1]=x1;    UPSTATE(b0v.x,b0v.y);
        ox[2]=x0;   oy[2]=x1;    UPSTATE(b0v.w,c0v.x);
        ox[3]=x0;   oy[3]=x1;    UPSTATE(c0v.z,c0v.w);
        ox[4]=x0;   oy[4]=x1;    UPSTATE(a1v.y,a1v.z);
        ox[5]=x0;   oy[5]=x1;    UPSTATE(b1v.x,b1v.y);
        ox[6]=x0;   oy[6]=x1;    UPSTATE(b1v.w,c1v.x);
        ox[7]=x0;   oy[7]=x1;    UPSTATE(c1v.z,c1v.w);
    }

    // ---- warp KS over per-lane offsets (segment = 8 steps) ----
    float v0=x0, v1=x1;
    #pragma unroll
    for (int r=0;r<5;r++){
        int off = 1<<r;
        float u0=__shfl_up_sync(0xffffffffu,v0,off);
        float u1=__shfl_up_sync(0xffffffffu,v1,off);
        if (lane>=off){
            float P0=sC.Tpow[3+r][0],P1=sC.Tpow[3+r][1],P2=sC.Tpow[3+r][2],P3=sC.Tpow[3+r][3];
            v0 = fmaf(P0,u0,fmaf(P1,u1,v0));
            v1 = fmaf(P2,u0,fmaf(P3,u1,v1));
        }
    }
    float ex0=__shfl_up_sync(0xffffffffu,v0,1);
    float ex1=__shfl_up_sync(0xffffffffu,v1,1);
    if (lane==0){ ex0=0.f; ex1=0.f; }

    // ---- thread entry = (M^8)^lane * warp_entry + exclusive prefix ----
    float e0=We0, e1=We1;
    #pragma unroll
    for (int r=0;r<5;r++) if ((lane>>r)&1){
        float P0=sC.Tpow[3+r][0],P1=sC.Tpow[3+r][1],P2=sC.Tpow[3+r][2],P3=sC.Tpow[3+r][3];
        float n0=fmaf(P0,e0,P1*e1), n1=fmaf(P2,e0,P3*e1);
        e0=n0; e1=n1;
    }
    e0 += ex0; e1 += ex1;

    // ---- outputs into the (now dead) input smem region, padded rows ----
    __syncwarp();   // all lanes finished reading their input rows
    {
        // padded layout: 16 rows x (8 payload f4 + 1 pad), 144 f4 < WARP_IN
        float4* orow = sin4 + (lane>>1)*9 + (lane&1)*4;
        float E0=e0, E1=e1;
        #pragma unroll
        for (int j=0;j<4;j++){
            float4 O;
            float xk0 = E0 + ox[2*j],   xk1 = E1 + oy[2*j];
            O.x = fmaf(c00,xk0,c01*xk1); O.y = fmaf(c10,xk0,c11*xk1);
            { float n0=fmaf(t00,E0,t01*E1), n1=fmaf(t10,E0,t11*E1); E0=n0; E1=n1; }
            xk0 = E0 + ox[2*j+1]; xk1 = E1 + oy[2*j+1];
            O.z = fmaf(c00,xk0,c01*xk1); O.w = fmaf(c10,xk0,c11*xk1);
            { float n0=fmaf(t00,E0,t01*E1), n1=fmaf(t10,E0,t11*E1); E0=n0; E1=n1; }
            orow[j] = O;
        }
    }
    __syncwarp();

    // ---- coalesced streaming store of the 2KB warp out tile ----
    float4* q4 = (float4*)out + (size_t)warpStepBase/2;
    #pragma unroll
    for (int i=0;i<4;i++){
        int q = lane + 32*i;
        __stcs(q4+q, sin4[(q>>3)*9 + (q&7)]);
    }
}

// --------------------------------------------------------------- launch ----
extern "C" void kernel_launch(void* const* d_in, const int* in_sizes, int n_in,
                              void* d_out, int out_size)
{
    const float* in  = (const float*)d_in[0];
    const float* A   = (const float*)d_in[1];
    const float* B   = (const float*)d_in[2];
    // d_in[3] = D (unused by the reference)
    const float* E   = (const float*)d_in[4];
    const float* cov = (const float*)d_in[5];
    const float* tp  = (const float*)d_in[6];
    const float* ini = (const float*)d_in[7];
    float* out = (float*)d_out;

    cudaFuncSetAttribute(k_pass3, cudaFuncAttributeMaxDynamicSharedMemorySize, P3_SMEM);

    k_pass1<<<NCTA,TPB>>>(in, A,B,E,cov,tp,ini);
    k_pass3<<<NCTA,TPB,P3_SMEM>>>(in, out, A,B,E,cov,tp,ini);
}

// round 15
// speedup vs baseline: 1.0418x; 1.0418x over previous
#include <cuda_runtime.h>
#include <math.h>
#include <stdint.h>

#define DTF       1e-4f
#define TSTEPS    4000000
#define TPB       256
#define STEPS_PER_CTA 2048
#define NCTA      1954            /* tiles: ceil(4e6/2048) */
#define NWTILE    (NCTA*8)        /* 256-step warp tiles */
#define NBLK      740             /* 148 SMs x 5 resident CTAs */

// staging smem geometry (float4 units) — input stage, reused as output stage
#define IN_ROW    7               /* 6 payload f4 + 1 pad */
#define WARP_IN   (32*IN_ROW)     /* 224 f4 = 3584 B */
#define DYN_SMEM  (8*WARP_IN*16)  /* 28672 B */

struct SC {
    float t00,t01,t10,t11;     // Trans
    float xi00,xi01,xi10,xi11; // XiCov
    float c00,c01,c10,c11;     // Cout
    float p0dt, p1, x00, x01;
    float cA, sA;              // 1-step forcing rotation
    float cR, sR;              // 32-step forcing rotation
    float Tpow[22][4];         // Tpow[r] = Trans^(2^r)
};

__device__ float2   g_wagg[NWTILE];   // per-warp (256-step) affine aggregate
__device__ float    g_csum[NCTA*2];   // per-tile affine aggregate
__device__ float    g_centry[NCTA*2]; // per-tile entry state
__device__ unsigned g_done;           // phase-1 completion counter
__device__ unsigned g_done2;          // phase-2 completion counter
__device__ unsigned g_phase;          // barrier flag

__device__ __forceinline__ void mat2mul(const float* a, const float* b, float* o) {
    o[0]=fmaf(a[0],b[0],a[1]*b[2]); o[1]=fmaf(a[0],b[1],a[1]*b[3]);
    o[2]=fmaf(a[2],b[0],a[3]*b[2]); o[3]=fmaf(a[2],b[1],a[3]*b[3]);
}

__device__ __forceinline__ void compute_consts(
    SC* s, int maxPow,
    const float* __restrict__ A, const float* __restrict__ B,
    const float* __restrict__ E, const float* __restrict__ cov,
    const float* __restrict__ tp, const float* __restrict__ ini)
{
    float a0=A[0],a1=A[1],a2=A[2],a3=A[3];
    float b0=B[0],b1=B[1],b2=B[2],b3=B[3];
    float e0=E[0],e1=E[1],e2=E[2],e3=E[3];
    float v0=cov[0],v1=cov[1],v2=cov[2],v3=cov[3];
    float s2 = sqrtf(2.0f);
    float cb0=fmaf(v0,b0,v1*b2), cb1=fmaf(v0,b1,v1*b3);
    float cb2=fmaf(v2,b0,v3*b2), cb3=fmaf(v2,b1,v3*b3);
    float xi0=(e0-cb0)/s2, xi1=(e1-cb1)/s2, xi2=(e2-cb2)/s2, xi3=(e3-cb3)/s2;
    float n0=-s2*b0, n1=-s2*b2, n2=-s2*b1, n3=-s2*b3;
    float xc0=fmaf(xi0,n0,xi1*n2), xc1=fmaf(xi0,n1,xi1*n3);
    float xc2=fmaf(xi2,n0,xi3*n2), xc3=fmaf(xi2,n1,xi3*n3);
    float tr[4] = { 1.0f + (a0-xc0)*DTF, (a1-xc1)*DTF,
                    (a2-xc2)*DTF, 1.0f + (a3-xc3)*DTF };
    s->t00=tr[0]; s->t01=tr[1]; s->t10=tr[2]; s->t11=tr[3];
    s->xi00=xi0; s->xi01=xi1; s->xi10=xi2; s->xi11=xi3;
    s->c00=n0*DTF; s->c01=n1*DTF; s->c10=n2*DTF; s->c11=n3*DTF;
    float p1f = tp[1];
    s->p0dt = tp[0]*DTF;
    s->p1   = p1f;
    s->x00  = ini[0]; s->x01 = ini[1];
    { float sr,cr; sincosf(p1f*DTF, &sr,&cr);        s->cA=cr; s->sA=sr; }
    { float sr,cr; sincosf(p1f*(DTF*32.f), &sr,&cr); s->cR=cr; s->sR=sr; }
    for (int i=0;i<4;i++) s->Tpow[0][i]=tr[i];
    for (int r=1;r<=maxPow;r++) mat2mul(s->Tpow[r-1], s->Tpow[r-1], s->Tpow[r]);
}

#define UPSTATE(d0,d1) do{                                            \
    float a0_ = fmaf(xi01,(d1),cc);  a0_ = fmaf(xi00,(d0),a0_);        \
    float a1_ = xi11*(d1);           a1_ = fmaf(xi10,(d0),a1_);        \
    float nx0_ = fmaf(t01,x1,a0_);   nx0_ = fmaf(t00,x0,nx0_);         \
    float nx1_ = fmaf(t11,x1,a1_);   nx1_ = fmaf(t10,x0,nx1_);         \
    x0=nx0_; x1=nx1_;                                                  \
    float nc_ = fmaf(cc,cA,-(ss*sA)); ss = fmaf(ss,cA,cc*sA); cc=nc_;  \
} while(0)

// ===================== persistent fused kernel =====================
__global__ void __launch_bounds__(TPB,5) k_fused(const float* __restrict__ in,
    float* __restrict__ out,
    const float* __restrict__ A, const float* __restrict__ B,
    const float* __restrict__ E, const float* __restrict__ cov,
    const float* __restrict__ tp, const float* __restrict__ ini)
{
    extern __shared__ float4 s4[];
    __shared__ SC sC;
    __shared__ float2 swarp[8];
    __shared__ float  sc[TPB], sd[TPB];
    __shared__ int    s_last;
    const int tid = threadIdx.x, blk = blockIdx.x;
    const int lane = tid & 31, wid = tid >> 5;

    if (tid==0) compute_consts(&sC, 21, A,B,E,cov,tp,ini);
    __syncthreads();

    // =========================== PHASE 1 ===========================
    {
        const float xi00=sC.xi00,xi01=sC.xi01,xi10=sC.xi10,xi11=sC.xi11;
        const float M0=sC.Tpow[5][0],M1=sC.Tpow[5][1],M2=sC.Tpow[5][2],M3=sC.Tpow[5][3];
        const float cR=sC.cR, sR=sC.sR, p0dt=sC.p0dt;

        for (int tile = blk; tile < NCTA; tile += NBLK){
            const int warpBase = tile*STEPS_PER_CTA + wid*256;

            float sv, cv;
            sincosf(sC.p1 * ((float)(warpBase+lane) * DTF), &sv, &cv);
            float cc = p0dt*cv, ss = p0dt*sv;

            float S0=0.f, S1=0.f;
            const float* p = in + (size_t)warpBase*3 + lane*3;
            #pragma unroll
            for (int j=0;j<8;j++){
                int k = warpBase + 32*j + lane;
                float b0=0.f, b1=0.f;
                if (k < TSTEPS){
                    float d0 = p[96*j+1];
                    float d1 = p[96*j+2];
                    b0 = fmaf(xi00,d0, fmaf(xi01,d1, cc));
                    b1 = fmaf(xi10,d0, xi11*d1);
                }
                float n0 = fmaf(M0,S0, fmaf(M1,S1, b0));
                float n1 = fmaf(M2,S0, fmaf(M3,S1, b1));
                S0=n0; S1=n1;
                float nc = fmaf(cc,cR,-(ss*sR)); ss = fmaf(ss,cR,cc*sR); cc=nc;
            }
            // in-warp weighted butterfly
            #pragma unroll
            for (int r=0;r<5;r++){
                float u0=__shfl_down_sync(0xffffffffu,S0,1<<r);
                float u1=__shfl_down_sync(0xffffffffu,S1,1<<r);
                float P0=sC.Tpow[r][0],P1=sC.Tpow[r][1],P2=sC.Tpow[r][2],P3=sC.Tpow[r][3];
                float n0 = fmaf(P0,S0, fmaf(P1,S1, u0));
                float n1 = fmaf(P2,S0, fmaf(P3,S1, u1));
                S0=n0; S1=n1;
            }
            if (lane==0){
                g_wagg[tile*8+wid] = make_float2(S0,S1);
                swarp[wid] = make_float2(S0,S1);
            }
            __syncthreads();
            if (wid==0 && lane<8){
                float2 R = swarp[lane];
                float R0=R.x, R1=R.y;
                #pragma unroll
                for (int r=0;r<3;r++){
                    float u0=__shfl_down_sync(0x000000ffu,R0,1<<r);
                    float u1=__shfl_down_sync(0x000000ffu,R1,1<<r);
                    float P0=sC.Tpow[8+r][0],P1=sC.Tpow[8+r][1],P2=sC.Tpow[8+r][2],P3=sC.Tpow[8+r][3];
                    float n0 = fmaf(P0,R0, fmaf(P1,R1, u0));
                    float n1 = fmaf(P2,R0, fmaf(P3,R1, u1));
                    R0=n0; R1=n1;
                }
                if (lane==0){ g_csum[2*tile]=R0; g_csum[2*tile+1]=R1; }
            }
            __syncthreads();   // swarp reuse across tile iterations
        }
    }

    // release all our stores, then count completion
    __threadfence();
    __syncthreads();
    if (tid==0){
        unsigned t = atomicAdd(&g_done, 1u);
        s_last = (t == NBLK-1u) ? 1 : 0;
    }
    __syncthreads();

    // ================== fused pass2 (last CTA only) =================
    if (s_last){
        __threadfence();
        const int g = tid;                 // chunk of 8 tiles: [8g, 8g+8)
        const float Tc0=sC.Tpow[11][0],Tc1=sC.Tpow[11][1],
                    Tc2=sC.Tpow[11][2],Tc3=sC.Tpow[11][3];
        float a[8][2];
        float v0=0.f, v1=0.f;
        #pragma unroll
        for (int i=0;i<8;i++){
            int t8 = 8*g+i;
            float a0 = (t8<NCTA)? __ldcg(&g_csum[2*t8])   : 0.f;
            float a1 = (t8<NCTA)? __ldcg(&g_csum[2*t8+1]) : 0.f;
            a[i][0]=a0; a[i][1]=a1;
            float n0 = fmaf(Tc0,v0, fmaf(Tc1,v1, a0));
            float n1 = fmaf(Tc2,v0, fmaf(Tc3,v1, a1));
            v0=n0; v1=n1;
        }
        sc[g]=v0; sd[g]=v1;
        __syncthreads();
        #pragma unroll
        for (int r=0;r<8;r++){
            int off = 1<<r;
            float u0=0.f, u1=0.f;
            if (g>=off){ u0=sc[g-off]; u1=sd[g-off]; }
            __syncthreads();
            float P0=sC.Tpow[14+r][0],P1=sC.Tpow[14+r][1],P2=sC.Tpow[14+r][2],P3=sC.Tpow[14+r][3];
            v0 = fmaf(P0,u0,fmaf(P1,u1,v0));
            v1 = fmaf(P2,u0,fmaf(P3,u1,v1));
            sc[g]=v0; sd[g]=v1;
            __syncthreads();
        }
        float pe0 = g ? sc[g-1] : 0.f;
        float pe1 = g ? sd[g-1] : 0.f;
        float X0=sC.x00, X1=sC.x01;
        #pragma unroll
        for (int r=0;r<8;r++) if ((g>>r)&1){
            float P0=sC.Tpow[14+r][0],P1=sC.Tpow[14+r][1],P2=sC.Tpow[14+r][2],P3=sC.Tpow[14+r][3];
            float n0=fmaf(P0,X0,P1*X1), n1=fmaf(P2,X0,P3*X1);
            X0=n0; X1=n1;
        }
        float E0 = pe0 + X0, E1 = pe1 + X1;
        #pragma unroll
        for (int i=0;i<8;i++){
            int t8 = 8*g+i;
            if (t8<NCTA){ g_centry[2*t8]=E0; g_centry[2*t8+1]=E1; }
            float n0 = fmaf(Tc0,E0, fmaf(Tc1,E1, a[i][0]));
            float n1 = fmaf(Tc2,E0, fmaf(Tc3,E1, a[i][1]));
            E0=n0; E1=n1;
        }
        __threadfence();
        __syncthreads();
        if (tid==0) atomicExch(&g_phase, 1u);
    }

    // ===================== software grid barrier ====================
    if (tid==0){
        while (atomicAdd(&g_phase, 0u) == 0u) __nanosleep(64);
    }
    __syncthreads();
    __threadfence();

    // =========================== PHASE 2 ===========================
    {
        const float t00=sC.t00,t01=sC.t01,t10=sC.t10,t11=sC.t11;
        const float xi00=sC.xi00,xi01=sC.xi01,xi10=sC.xi10,xi11=sC.xi11;
        const float c00=sC.c00,c01=sC.c01,c10=sC.c10,c11=sC.c11;
        const float cA=sC.cA, sA=sC.sA, p0dt=sC.p0dt;
        float4* sin4 = s4 + wid*WARP_IN;

        for (int tile = blk; tile < NCTA; tile += NBLK){
            const int warpStepBase = tile*STEPS_PER_CTA + wid*256;
            const bool wfull = (warpStepBase + 256 <= TSTEPS);
            if (!wfull) continue;

            // ---- async stage input ----
            {
                uint32_t sbase;
                asm("{ .reg .u64 t; cvta.to.shared.u64 t, %1; cvt.u32.u64 %0, t; }"
                    : "=r"(sbase) : "l"(sin4));
                const float4* p4 = (const float4*)in + (size_t)warpStepBase*3/4;
                #pragma unroll
                for (int i=0;i<6;i++){
                    int q = lane + 32*i;
                    int to = q/6, c = q - to*6;
                    uint32_t dst = sbase + (uint32_t)(to*IN_ROW + c)*16u;
                    asm volatile("cp.async.cg.shared.global [%0],[%1],16;"
                                 :: "r"(dst), "l"(p4+q));
                }
                asm volatile("cp.async.commit_group;" ::: "memory");
            }

            // ---- warp entry while TMA-ish copy lands ----
            float We0, We1;
            {
                float w0=0.f, w1=0.f;
                if (lane < 8){ float2 wa = g_wagg[tile*8+lane]; w0=wa.x; w1=wa.y; }
                #pragma unroll
                for (int r=0;r<3;r++){
                    int off = 1<<r;
                    float u0=__shfl_up_sync(0xffffffffu,w0,off);
                    float u1=__shfl_up_sync(0xffffffffu,w1,off);
                    if (lane>=off){
                        float P0=sC.Tpow[8+r][0],P1=sC.Tpow[8+r][1],P2=sC.Tpow[8+r][2],P3=sC.Tpow[8+r][3];
                        w0 = fmaf(P0,u0,fmaf(P1,u1,w0));
                        w1 = fmaf(P2,u0,fmaf(P3,u1,w1));
                    }
                }
                float pf0=__shfl_up_sync(0xffffffffu,w0,1);
                float pf1=__shfl_up_sync(0xffffffffu,w1,1);
                if (lane==0){ pf0=0.f; pf1=0.f; }
                float X0=g_centry[2*tile], X1=g_centry[2*tile+1];
                #pragma unroll
                for (int r=0;r<3;r++) if ((lane>>r)&1){
                    float P0=sC.Tpow[8+r][0],P1=sC.Tpow[8+r][1],P2=sC.Tpow[8+r][2],P3=sC.Tpow[8+r][3];
                    float n0=fmaf(P0,X0,P1*X1), n1=fmaf(P2,X0,P3*X1);
                    X0=n0; X1=n1;
                }
                float e0 = X0 + pf0, e1 = X1 + pf1;
                We0 = __shfl_sync(0xffffffffu, e0, wid);
                We1 = __shfl_sync(0xffffffffu, e1, wid);
            }

            asm volatile("cp.async.wait_group 0;" ::: "memory");
            __syncwarp();

            // ---- offset pass from x=0 ----
            float ox[8], oy[8];
            float x0=0.f, x1=0.f;
            float cc, ss;
            {
                const float4* row = sin4 + lane*IN_ROW;
                float4 a0v=row[0], b0v=row[1], c0v=row[2];
                float4 a1v=row[3], b1v=row[4], c1v=row[5];
                float sv, cvv; sincosf(sC.p1 * a0v.x, &sv, &cvv);
                cc = p0dt*cvv; ss = p0dt*sv;
                ox[0]=0.f;  oy[0]=0.f;   UPSTATE(a0v.y,a0v.z);
                ox[1]=x0;   oy[1]=x1;    UPSTATE(b0v.x,b0v.y);
                ox[2]=x0;   oy[2]=x1;    UPSTATE(b0v.w,c0v.x);
                ox[3]=x0;   oy[3]=x1;    UPSTATE(c0v.z,c0v.w);
                ox[4]=x0;   oy[4]=x1;    UPSTATE(a1v.y,a1v.z);
                ox[5]=x0;   oy[5]=x1;    UPSTATE(b1v.x,b1v.y);
                ox[6]=x0;   oy[6]=x1;    UPSTATE(b1v.w,c1v.x);
                ox[7]=x0;   oy[7]=x1;    UPSTATE(c1v.z,c1v.w);
            }

            // ---- warp KS over per-lane offsets ----
            float v0=x0, v1=x1;
            #pragma unroll
            for (int r=0;r<5;r++){
                int off = 1<<r;
                float u0=__shfl_up_sync(0xffffffffu,v0,off);
                float u1=__shfl_up_sync(0xffffffffu,v1,off);
                if (lane>=off){
                    float P0=sC.Tpow[3+r][0],P1=sC.Tpow[3+r][1],P2=sC.Tpow[3+r][2],P3=sC.Tpow[3+r][3];
                    v0 = fmaf(P0,u0,fmaf(P1,u1,v0));
                    v1 = fmaf(P2,u0,fmaf(P3,u1,v1));
                }
            }
            float ex0=__shfl_up_sync(0xffffffffu,v0,1);
            float ex1=__shfl_up_sync(0xffffffffu,v1,1);
            if (lane==0){ ex0=0.f; ex1=0.f; }

            // ---- thread entry ----
            float e0=We0, e1=We1;
            #pragma unroll
            for (int r=0;r<5;r++) if ((lane>>r)&1){
                float P0=sC.Tpow[3+r][0],P1=sC.Tpow[3+r][1],P2=sC.Tpow[3+r][2],P3=sC.Tpow[3+r][3];
                float n0=fmaf(P0,e0,P1*e1), n1=fmaf(P2,e0,P3*e1);
                e0=n0; e1=n1;
            }
            e0 += ex0; e1 += ex1;

            // ---- outputs into the dead input smem region ----
            __syncwarp();
            {
                float4* orow = sin4 + (lane>>1)*9 + (lane&1)*4;
                float E0=e0, E1=e1;
                #pragma unroll
                for (int j=0;j<4;j++){
                    float4 O;
                    float xk0 = E0 + ox[2*j],   xk1 = E1 + oy[2*j];
                    O.x = fmaf(c00,xk0,c01*xk1); O.y = fmaf(c10,xk0,c11*xk1);
                    { float n0=fmaf(t00,E0,t01*E1), n1=fmaf(t10,E0,t11*E1); E0=n0; E1=n1; }
                    xk0 = E0 + ox[2*j+1]; xk1 = E1 + oy[2*j+1];
                    O.z = fmaf(c00,xk0,c01*xk1); O.w = fmaf(c10,xk0,c11*xk1);
                    { float n0=fmaf(t00,E0,t01*E1), n1=fmaf(t10,E0,t11*E1); E0=n0; E1=n1; }
                    orow[j] = O;
                }
            }
            __syncwarp();

            // ---- coalesced streaming store ----
            float4* q4 = (float4*)out + (size_t)warpStepBase/2;
            #pragma unroll
            for (int i=0;i<4;i++){
                int q = lane + 32*i;
                __stcs(q4+q, sin4[(q>>3)*9 + (q&7)]);
            }
            __syncwarp();   // staging reuse next tile
        }
    }

    // ---- replay-safe reset by the very last CTA ----
    __syncthreads();
    if (tid==0){
        unsigned t = atomicAdd(&g_done2, 1u);
        if (t == NBLK-1u){
            g_done = 0u; g_done2 = 0u;
            atomicExch(&g_phase, 0u);
        }
    }
}

// --------------------------------------------------------------- launch ----
extern "C" void kernel_launch(void* const* d_in, const int* in_sizes, int n_in,
                              void* d_out, int out_size)
{
    const float* in  = (const float*)d_in[0];
    const float* A   = (const float*)d_in[1];
    const float* B   = (const float*)d_in[2];
    // d_in[3] = D (unused by the reference)
    const float* E   = (const float*)d_in[4];
    const float* cov = (const float*)d_in[5];
    const float* tp  = (const float*)d_in[6];
    const float* ini = (const float*)d_in[7];
    float* out = (float*)d_out;

    cudaFuncSetAttribute(k_fused, cudaFuncAttributeMaxDynamicSharedMemorySize, DYN_SMEM);

    k_fused<<<NBLK,TPB,DYN_SMEM>>>(in, out, A,B,E,cov,tp,ini);
}